// round 9
// baseline (speedup 1.0000x reference)
#include <cuda_runtime.h>
#include <stdint.h>

// GreedyGroupedRouter: SEQ=524288 tokens, 256 experts, 8 groups of 32, top-1/group.
// d_out layout (float32): rw[SEQ*256] | tw[SEQ*8] | tids[SEQ*8] | hist[256]
//
// R1 champion router body, R8 single-node fusion, grid reshaped to EXACTLY one
// wave: 592 blocks = 148 SMs x 4 resident blocks (256 thr = 8 warps, 32/SM).
// Removes the wave transition and halves the global-atomic histogram tail.

#define SEQ     524288
#define NE      256
#define NG      8
#define GS      32
#define TOPK    8

__device__ unsigned g_hist_ready = 0;
__device__ unsigned g_done_blocks = 0;

__global__ void __launch_bounds__(256)
router_kernel(const float* __restrict__ logits,
              float* __restrict__ rw,     // [SEQ, 256]
              float* __restrict__ tw,     // [SEQ, 8]
              float* __restrict__ tids,   // [SEQ, 8]
              float* __restrict__ hist)   // [256]
{
    __shared__ unsigned int shist[NE];
    for (int i = threadIdx.x; i < NE; i += blockDim.x) shist[i] = 0u;

    // Block 0 zeroes the global histogram, then publishes.
    if (blockIdx.x == 0) {
        hist[threadIdx.x] = 0.0f;         // blockDim.x == NE == 256
        __syncthreads();
        if (threadIdx.x == 0) {
            __threadfence();
            atomicExch(&g_hist_ready, 1u);
        }
    } else {
        __syncthreads();
    }

    const int lane   = threadIdx.x & 31;
    const int gwarp  = blockIdx.x * (blockDim.x >> 5) + (threadIdx.x >> 5);
    const int nwarps = gridDim.x * (blockDim.x >> 5);

    for (int row = gwarp; row < SEQ; row += nwarps) {
        const float* lp = logits + (size_t)row * NE;

        // Lane-strided: lane holds element (lane + 32*i); register i is this
        // lane's member of expert-group i. Each load is a coalesced 128B.
        float x[NG];
        #pragma unroll
        for (int i = 0; i < NG; i++) x[i] = lp[lane + GS * i];

        // Row max (softmax stabilization)
        float m = x[0];
        #pragma unroll
        for (int i = 1; i < NG; i++) m = fmaxf(m, x[i]);
        #pragma unroll
        for (int o = 16; o > 0; o >>= 1)
            m = fmaxf(m, __shfl_xor_sync(0xffffffffu, m, o));

        // exp + row sum
        float e[NG];
        float s = 0.0f;
        #pragma unroll
        for (int i = 0; i < NG; i++) { e[i] = __expf(x[i] - m); s += e[i]; }
        #pragma unroll
        for (int o = 16; o > 0; o >>= 1)
            s += __shfl_xor_sync(0xffffffffu, s, o);
        const float inv = 1.0f / s;

        // Softmax weights + immediate streaming store of routing_weights
        float* rp = rw + (size_t)row * NE;
        float w[NG];
        #pragma unroll
        for (int i = 0; i < NG; i++) {
            w[i] = e[i] * inv;
            rp[lane + GS * i] = w[i];
        }

        // Per-group argmax (group g = lanes' w[g]); tie-break to lowest index,
        // matching lax.top_k. Softmax values in (0,1] -> float bits monotone.
        float myw  = 0.0f;   // valid on lanes 0..7
        float myid = 0.0f;
        float sw   = 0.0f;
        #pragma unroll
        for (int g = 0; g < NG; g++) {
            unsigned u    = __float_as_uint(w[g]);
            unsigned umax = __reduce_max_sync(0xffffffffu, u);
            unsigned bal  = __ballot_sync(0xffffffffu, u == umax);
            int src       = __ffs(bal) - 1;           // lowest winning lane
            float gv      = __uint_as_float(umax);
            sw += gv;
            if (lane == g) { myw = gv; myid = (float)(g * GS + src); }
            if (lane == src) atomicAdd(&shist[g * GS + src], 1u);
        }
        const float invsw = 1.0f / (sw + 1e-20f);

        if (lane < TOPK) {
            tw[(size_t)row * TOPK + lane]   = myw * invsw;
            tids[(size_t)row * TOPK + lane] = myid;
        }
    }

    __syncthreads();

    // Flush: wait (already set in practice) for hist to be zeroed.
    if (threadIdx.x == 0) {
        while (atomicAdd(&g_hist_ready, 0u) == 0u) __nanosleep(64);
        __threadfence();
    }
    __syncthreads();

    for (int i = threadIdx.x; i < NE; i += blockDim.x) {
        unsigned c = shist[i];
        if (c) atomicAdd(&hist[i], (float)c);
    }

    __syncthreads();
    if (threadIdx.x == 0) {
        __threadfence();
        unsigned d = atomicAdd(&g_done_blocks, 1u);
        if (d == gridDim.x - 1) {           // last block resets for next replay
            atomicExch(&g_done_blocks, 0u);
            atomicExch(&g_hist_ready, 0u);
        }
    }
}

extern "C" void kernel_launch(void* const* d_in, const int* in_sizes, int n_in,
                              void* d_out, int out_size) {
    const float* logits = (const float*)d_in[0];
    float* out  = (float*)d_out;
    float* rw   = out;
    float* tw   = rw   + (size_t)SEQ * NE;
    float* tids = tw   + (size_t)SEQ * TOPK;
    float* hist = tids + (size_t)SEQ * TOPK;

    // Exactly one wave: 148 SMs x 4 blocks (8 warps each, 32 warps/SM).
    // 4736 warps, ~110.7 rows/warp grid-stride.
    router_kernel<<<592, 256>>>(logits, rw, tw, tids, hist);
}

// round 10
// speedup vs baseline: 1.1948x; 1.1948x over previous
#include <cuda_runtime.h>
#include <stdint.h>

// GreedyGroupedRouter: SEQ=524288 tokens, 256 experts, 8 groups of 32, top-1/group.
// d_out layout (float32): rw[SEQ*256] | tw[SEQ*8] | tids[SEQ*8] | hist[256]
//
// R1 champion router body + R8 single-node fusion, grid corrected to the real
// chip shape learned in R9: GB300 = 152 SMs, 64 warps/SM resident -> one full
// wave = 152 x 8 blocks = 1216 (256 thr each). 4864 warps, 107.76 rows/warp.

#define SEQ     524288
#define NE      256
#define NG      8
#define GS      32
#define TOPK    8

__device__ unsigned g_hist_ready = 0;
__device__ unsigned g_done_blocks = 0;

__global__ void __launch_bounds__(256)
router_kernel(const float* __restrict__ logits,
              float* __restrict__ rw,     // [SEQ, 256]
              float* __restrict__ tw,     // [SEQ, 8]
              float* __restrict__ tids,   // [SEQ, 8]
              float* __restrict__ hist)   // [256]
{
    __shared__ unsigned int shist[NE];
    for (int i = threadIdx.x; i < NE; i += blockDim.x) shist[i] = 0u;

    // Block 0 zeroes the global histogram, then publishes.
    if (blockIdx.x == 0) {
        hist[threadIdx.x] = 0.0f;         // blockDim.x == NE == 256
        __syncthreads();
        if (threadIdx.x == 0) {
            __threadfence();
            atomicExch(&g_hist_ready, 1u);
        }
    } else {
        __syncthreads();
    }

    const int lane   = threadIdx.x & 31;
    const int gwarp  = blockIdx.x * (blockDim.x >> 5) + (threadIdx.x >> 5);
    const int nwarps = gridDim.x * (blockDim.x >> 5);

    for (int row = gwarp; row < SEQ; row += nwarps) {
        const float* lp = logits + (size_t)row * NE;

        // Lane-strided: lane holds element (lane + 32*i); register i is this
        // lane's member of expert-group i. Each load is a coalesced 128B.
        float x[NG];
        #pragma unroll
        for (int i = 0; i < NG; i++) x[i] = lp[lane + GS * i];

        // Row max (softmax stabilization)
        float m = x[0];
        #pragma unroll
        for (int i = 1; i < NG; i++) m = fmaxf(m, x[i]);
        #pragma unroll
        for (int o = 16; o > 0; o >>= 1)
            m = fmaxf(m, __shfl_xor_sync(0xffffffffu, m, o));

        // exp + row sum
        float e[NG];
        float s = 0.0f;
        #pragma unroll
        for (int i = 0; i < NG; i++) { e[i] = __expf(x[i] - m); s += e[i]; }
        #pragma unroll
        for (int o = 16; o > 0; o >>= 1)
            s += __shfl_xor_sync(0xffffffffu, s, o);
        const float inv = 1.0f / s;

        // Softmax weights + immediate streaming store of routing_weights
        float* rp = rw + (size_t)row * NE;
        float w[NG];
        #pragma unroll
        for (int i = 0; i < NG; i++) {
            w[i] = e[i] * inv;
            rp[lane + GS * i] = w[i];
        }

        // Per-group argmax (group g = lanes' w[g]); tie-break to lowest index,
        // matching lax.top_k. Softmax values in (0,1] -> float bits monotone.
        float myw  = 0.0f;   // valid on lanes 0..7
        float myid = 0.0f;
        float sw   = 0.0f;
        #pragma unroll
        for (int g = 0; g < NG; g++) {
            unsigned u    = __float_as_uint(w[g]);
            unsigned umax = __reduce_max_sync(0xffffffffu, u);
            unsigned bal  = __ballot_sync(0xffffffffu, u == umax);
            int src       = __ffs(bal) - 1;           // lowest winning lane
            float gv      = __uint_as_float(umax);
            sw += gv;
            if (lane == g) { myw = gv; myid = (float)(g * GS + src); }
            if (lane == src) atomicAdd(&shist[g * GS + src], 1u);
        }
        const float invsw = 1.0f / (sw + 1e-20f);

        if (lane < TOPK) {
            tw[(size_t)row * TOPK + lane]   = myw * invsw;
            tids[(size_t)row * TOPK + lane] = myid;
        }
    }

    __syncthreads();

    // Flush: wait (already set in practice) for hist to be zeroed.
    if (threadIdx.x == 0) {
        while (atomicAdd(&g_hist_ready, 0u) == 0u) __nanosleep(64);
        __threadfence();
    }
    __syncthreads();

    for (int i = threadIdx.x; i < NE; i += blockDim.x) {
        unsigned c = shist[i];
        if (c) atomicAdd(&hist[i], (float)c);
    }

    __syncthreads();
    if (threadIdx.x == 0) {
        __threadfence();
        unsigned d = atomicAdd(&g_done_blocks, 1u);
        if (d == gridDim.x - 1) {           // last block resets for next replay
            atomicExch(&g_done_blocks, 0u);
            atomicExch(&g_hist_ready, 0u);
        }
    }
}

extern "C" void kernel_launch(void* const* d_in, const int* in_sizes, int n_in,
                              void* d_out, int out_size) {
    const float* logits = (const float*)d_in[0];
    float* out  = (float*)d_out;
    float* rw   = out;
    float* tw   = rw   + (size_t)SEQ * NE;
    float* tids = tw   + (size_t)SEQ * TOPK;
    float* hist = tids + (size_t)SEQ * TOPK;

    // One full wave on GB300: 152 SMs x 8 blocks = 1216 (64 warps/SM).
    router_kernel<<<1216, 256>>>(logits, rw, tw, tids, hist);
}